// round 8
// baseline (speedup 1.0000x reference)
#include <cuda_runtime.h>
#include <cstdint>

#define Bq 128
#define Tq 512
#define TAGq 256
#define START_TAG 254
#define STOP_TAG 255
#define NTHREADS 512       // warp-pair j-split: t2 = tid>>1, half = tid&1
#define TSTRIDE 136        // floats per tile row; half-1 section at offset 68

// Scratch (allocation-free rule: static __device__ globals)
__device__ float g_hist[(size_t)Bq * Tq * TAGq];   // partition history, 64 MB
__device__ float g_transT[TAGq * TAGq];            // transposed transitions

__device__ __forceinline__ float2 fadd2_(float2 a, float2 b) {
    float2 o;
    asm("{\n\t"
        ".reg .b64 ra, rb, rc;\n\t"
        "mov.b64 ra, {%2,%3};\n\t"
        "mov.b64 rb, {%4,%5};\n\t"
        "add.rn.f32x2 rc, ra, rb;\n\t"
        "mov.b64 {%0,%1}, rc;\n\t"
        "}"
        : "=f"(o.x), "=f"(o.y)
        : "f"(a.x), "f"(a.y), "f"(b.x), "f"(b.y));
    return o;
}

__device__ __forceinline__ float neg_inf() { return __int_as_float(0xff800000u); }

// Strictly order-preserving float -> u32 key (finite values, no NaN here).
__device__ __forceinline__ unsigned okey(float f) {
    unsigned u = __float_as_uint(f);
    return (u & 0x80000000u) ? ~u : (u | 0x80000000u);
}

// ---------------------------------------------------------------------------
// transT[t2][j] = trans[j][t2]
__global__ void transpose_kernel(const float* __restrict__ trans) {
    int j  = blockIdx.x;
    int t2 = threadIdx.x;
    g_transT[t2 * TAGq + j] = trans[j * TAGq + t2];
}

// ---------------------------------------------------------------------------
// Forward Viterbi: one CTA per batch, 512 threads.
// Thread pair (t2 = tid>>1, half = tid&1): each thread reduces j in
// [half*128, half*128+128); halves combined with one shfl_xor -> ONE
// __syncthreads per step.
// trans[j..j+64)   -> 16 float4 REGISTERS (loop-invariant, loaded once)
// trans[j+64..128) -> SMEM tile [256][TSTRIDE], half-1 section at float 68
// part[]           -> SMEM
__global__ __launch_bounds__(NTHREADS, 1)
void forward_kernel(const float* __restrict__ feats,
                    const float* __restrict__ trans) {
    extern __shared__ float smem_f[];
    float* tile  = smem_f;                     // [256][TSTRIDE]
    float* partA = smem_f + TAGq * TSTRIDE;    // 256
    float* partB = partA + TAGq;               // 256

    const int b    = blockIdx.x;
    const int tid  = threadIdx.x;
    const int t2   = tid >> 1;
    const int half = tid & 1;

    // Stage compacted tile:
    //   dest f4 [0,16)  <- transT f4 [16,32)  (orig cols  64..127)
    //   dest f4 [17,33) <- transT f4 [48,64)  (orig cols 192..255)
    for (int idx = tid; idx < TAGq * 32; idx += NTHREADS) {
        int r = idx >> 5, c4 = idx & 31;
        int dst4 = (c4 < 16) ? c4 : (c4 + 1);
        int src4 = (c4 < 16) ? (c4 + 16) : (c4 + 32);
        ((float4*)(tile + r * TSTRIDE))[dst4] =
            ((const float4*)g_transT)[r * 64 + src4];
    }

    // Register-resident trans slice: transT[t2][half*128 .. half*128+64)
    float4 tr4[16];
    {
        const float4* src = (const float4*)(g_transT + (size_t)t2 * TAGq) + half * 32;
        #pragma unroll
        for (int k = 0; k < 16; ++k) tr4[k] = src[k];
    }

    const float* febase = feats + (size_t)b * Tq * TAGq;
    float*       hbase  = g_hist + (size_t)b * Tq * TAGq;

    // part0 = feats[b,0,:] + trans[START,:]  (half-0 thread of each pair)
    if (half == 0) {
        float p0 = febase[t2] + trans[START_TAG * TAGq + t2];
        partA[t2] = p0;
        hbase[t2] = p0;
    }

    // prefetch emission for t = 1
    float e = __ldcs(febase + (size_t)TAGq + t2);
    __syncthreads();

    const float4* trow_s = (const float4*)(tile + t2 * TSTRIDE + half * 68);

    float* cur = partA;
    float* nxt = partB;

    for (int t = 1; t < Tq; ++t) {
        // prefetch next step's emission (one full step of latency slack)
        const int tn = (t + 1 < Tq) ? (t + 1) : t;
        float e_nxt = __ldcs(febase + (size_t)tn * TAGq + t2);

        const float2 e2 = make_float2(e, e);
        const float4* p4 = (const float4*)cur + half * 32;

        float a0 = neg_inf(), a1 = a0, a2 = a0, a3 = a0;
        float a4 = a0, a5 = a0, a6 = a0, a7 = a0;

        // j local [0,64): trans from registers
        #pragma unroll
        for (int k = 0; k < 16; ++k) {
            float4 pa = p4[k];
            float4 ta = tr4[k];
            float2 s;
            s = fadd2_(fadd2_(e2, make_float2(ta.x, ta.y)), make_float2(pa.x, pa.y));
            a0 = fmaxf(a0, s.x); a1 = fmaxf(a1, s.y);
            s = fadd2_(fadd2_(e2, make_float2(ta.z, ta.w)), make_float2(pa.z, pa.w));
            a2 = fmaxf(a2, s.x); a3 = fmaxf(a3, s.y);
        }
        // j local [64,128): trans from SMEM tile
        #pragma unroll
        for (int k = 0; k < 16; ++k) {
            float4 pb = p4[16 + k];
            float4 tb = trow_s[k];
            float2 s;
            s = fadd2_(fadd2_(e2, make_float2(tb.x, tb.y)), make_float2(pb.x, pb.y));
            a4 = fmaxf(a4, s.x); a5 = fmaxf(a5, s.y);
            s = fadd2_(fadd2_(e2, make_float2(tb.z, tb.w)), make_float2(pb.z, pb.w));
            a6 = fmaxf(a6, s.x); a7 = fmaxf(a7, s.y);
        }
        float m = fmaxf(fmaxf(fmaxf(a0, a1), fmaxf(a2, a3)),
                        fmaxf(fmaxf(a4, a5), fmaxf(a6, a7)));

        // combine the two halves within the pair (lanes 2k, 2k+1)
        float other = __shfl_xor_sync(0xffffffffu, m, 1);
        float mm = fmaxf(m, other);

        if (half == 0) {
            nxt[t2] = mm;
            hbase[(size_t)t * TAGq + t2] = mm;
        }
        __syncthreads();

        float* tp = cur; cur = nxt; nxt = tp;
        e = e_nxt;
    }
}

// ---------------------------------------------------------------------------
// Warp argmax over 256 contiguous values (8 per lane, ascending j), with
// jnp.argmax first-index semantics: lane-local strict-greater ascending scan,
// then redux-max on an order-preserving key; lowest matching lane wins ties.
__device__ __forceinline__ int warp_argmax256(float xv, int xi, float* vmax_out) {
    unsigned kk   = okey(xv);
    unsigned kmax = __reduce_max_sync(0xffffffffu, kk);
    unsigned bal  = __ballot_sync(0xffffffffu, kk == kmax);
    int src = __ffs((int)bal) - 1;
    if (vmax_out)
        *vmax_out = __shfl_sync(0xffffffffu, xv, src);
    return __shfl_sync(0xffffffffu, xi, src);
}

// One warp per batch: final score + full backtrace with bp recomputation.
__global__ void backward_kernel(const float* __restrict__ feats,
                                const int*   __restrict__ mask,
                                float*       __restrict__ out) {
    const int b = blockIdx.x, lane = threadIdx.x;

    // lengths = sum(mask[b,:])  (also warms the mask row into L1)
    int len = 0;
    for (int i = lane; i < Tq; i += 32) len += mask[b * Tq + i];
    #pragma unroll
    for (int o = 16; o; o >>= 1) len += __shfl_down_sync(0xffffffffu, len, o);
    len = __shfl_sync(0xffffffffu, len, 0);
    const int last = len - 1;

    const float* hb = g_hist + (size_t)b * Tq * TAGq;

    // path score / pointer: argmax_j last_part[j] + trans[j][STOP]
    int ptr;
    {
        const float4* lp4 = (const float4*)(hb + (size_t)last * TAGq) + lane * 2;
        const float4* tc4 = (const float4*)(g_transT + STOP_TAG * TAGq) + lane * 2;
        float4 A = lp4[0], B = lp4[1], C = tc4[0], D = tc4[1];
        float v[8] = {A.x + C.x, A.y + C.y, A.z + C.z, A.w + C.w,
                      B.x + D.x, B.y + D.y, B.z + D.z, B.w + D.w};
        float xv = v[0]; int xi = lane * 8;
        #pragma unroll
        for (int k = 1; k < 8; ++k)
            if (v[k] > xv) { xv = v[k]; xi = lane * 8 + k; }
        float bv;
        ptr = warp_argmax256(xv, xi, &bv);
        if (lane == 0) out[b] = bv;
    }

    float* dec = out + Bq;
    if (lane == 0) dec[(size_t)b * Tq + (Tq - 1)] = (float)ptr;

    int cur = ptr;
    for (int i = Tq - 2; i >= 0; --i) {
        // Prefetch-touch rows needed at iteration i-1 (index-predictable,
        // independent of cur): feats[b, i, :] and hist[b, i-1, :].
        // 32 lanes x stride-8 floats = one touch per 32B sector of each 1KB row.
        {
            float d0;
            const float* fr = feats + ((size_t)b * Tq + i) * TAGq + lane * 8;
            asm volatile("ld.global.nc.f32 %0, [%1];" : "=f"(d0) : "l"(fr));
            if (i >= 1) {
                float d1;
                const float* hr = hb + (size_t)(i - 1) * TAGq + lane * 8;
                asm volatile("ld.global.nc.f32 %0, [%1];" : "=f"(d1) : "l"(hr));
            }
        }

        int nv;
        if (i == last) {
            nv = ptr;
        } else if (mask[b * Tq + i + 1] == 0) {
            nv = 0;
        } else {
            // recompute bp at time i+1, column cur — identical arithmetic
            // to the forward pass: (emit + trans) + part
            const float e =
                __ldg(feats + ((size_t)b * Tq + (i + 1)) * TAGq + cur);
            const float4* h4 = (const float4*)(hb + (size_t)i * TAGq) + lane * 2;
            const float4* t4 =
                (const float4*)(g_transT + (size_t)cur * TAGq) + lane * 2;
            float4 H0 = h4[0], H1 = h4[1], T0 = t4[0], T1 = t4[1];
            float v[8] = {(e + T0.x) + H0.x, (e + T0.y) + H0.y,
                          (e + T0.z) + H0.z, (e + T0.w) + H0.w,
                          (e + T1.x) + H1.x, (e + T1.y) + H1.y,
                          (e + T1.z) + H1.z, (e + T1.w) + H1.w};
            float xv = v[0]; int xi = lane * 8;
            #pragma unroll
            for (int k = 1; k < 8; ++k)
                if (v[k] > xv) { xv = v[k]; xi = lane * 8 + k; }
            nv = warp_argmax256(xv, xi, nullptr);
        }
        cur = nv;
        if (lane == 0) dec[(size_t)b * Tq + i] = (float)cur;
    }
}

// ---------------------------------------------------------------------------
extern "C" void kernel_launch(void* const* d_in, const int* in_sizes, int n_in,
                              void* d_out, int out_size) {
    const float* feats = (const float*)d_in[0];   // (128,512,256) f32
    const int*   mask  = (const int*)d_in[1];     // (128,512) i32
    const float* trans = (const float*)d_in[2];   // (256,256) f32
    float* out = (float*)d_out;                   // [128 path_score | 128*512 decode]

    transpose_kernel<<<TAGq, TAGq>>>(trans);

    const size_t smem =
        (size_t)(TAGq * TSTRIDE + 2 * TAGq) * sizeof(float); // 141312 B
    cudaFuncSetAttribute(forward_kernel,
                         cudaFuncAttributeMaxDynamicSharedMemorySize, (int)smem);
    forward_kernel<<<Bq, NTHREADS, smem>>>(feats, trans);

    backward_kernel<<<Bq, 32>>>(feats, mask, out);
}

// round 9
// speedup vs baseline: 1.2682x; 1.2682x over previous
#include <cuda_runtime.h>
#include <cstdint>

#define Bq 128
#define Tq 512
#define TAGq 256
#define START_TAG 254
#define STOP_TAG 255
#define NTHREADS 512       // 2-way j-split: tid = half*256 + t2
#define TSTRIDE 132        // floats per tile row = 33 float4 (conflict-free .128)

// Scratch (allocation-free rule: static __device__ globals)
__device__ float g_hist[(size_t)Bq * Tq * TAGq];   // partition history, 64 MB
__device__ float g_transT[TAGq * TAGq];            // transposed transitions

__device__ __forceinline__ float2 fadd2_(float2 a, float2 b) {
    float2 o;
    asm("{\n\t"
        ".reg .b64 ra, rb, rc;\n\t"
        "mov.b64 ra, {%2,%3};\n\t"
        "mov.b64 rb, {%4,%5};\n\t"
        "add.rn.f32x2 rc, ra, rb;\n\t"
        "mov.b64 {%0,%1}, rc;\n\t"
        "}"
        : "=f"(o.x), "=f"(o.y)
        : "f"(a.x), "f"(a.y), "f"(b.x), "f"(b.y));
    return o;
}

__device__ __forceinline__ float neg_inf() { return __int_as_float(0xff800000u); }

// Strictly order-preserving float -> u32 key (finite values, no NaN here).
__device__ __forceinline__ unsigned okey(float f) {
    unsigned u = __float_as_uint(f);
    return (u & 0x80000000u) ? ~u : (u | 0x80000000u);
}

// ---------------------------------------------------------------------------
// transT[t2][j] = trans[j][t2]
__global__ void transpose_kernel(const float* __restrict__ trans) {
    int j  = blockIdx.x;
    int t2 = threadIdx.x;
    g_transT[t2 * TAGq + j] = trans[j * TAGq + t2];
}

// ---------------------------------------------------------------------------
// Forward Viterbi (R5 structure — measured-good): one CTA per batch, 512 thr.
// Thread (half = tid>>8, t2 = tid&255) reduces j in [half*128, half*128+128).
// trans[j..j+64)   -> 16 float4 REGISTERS (loop-invariant, loaded once)
// trans[j+64..128) -> SMEM tile (compacted: 128 cols/row, stride 132)
// part[]           -> SMEM, warp-broadcast loads (half uniform per warp)
__global__ __launch_bounds__(NTHREADS, 1)
void forward_kernel(const float* __restrict__ feats,
                    const float* __restrict__ trans) {
    extern __shared__ float smem_f[];
    float* tile    = smem_f;                        // [256][TSTRIDE]
    float* partA   = smem_f + TAGq * TSTRIDE;       // 256
    float* partB   = partA + TAGq;                  // 256
    float* partial = partB + TAGq;                  // 512

    const int b    = blockIdx.x;
    const int tid  = threadIdx.x;
    const int t2   = tid & 255;
    const int half = tid >> 8;

    // Stage compacted tile: tile[r][0:16) f4 = transT[r][16:32) f4 (orig cols 64..127)
    //                       tile[r][16:32) f4 = transT[r][48:64) f4 (orig cols 192..255)
    for (int idx = tid; idx < TAGq * 32; idx += NTHREADS) {
        int r = idx >> 5, c4 = idx & 31;
        int src4 = (c4 < 16) ? (c4 + 16) : (c4 + 32);
        ((float4*)(tile + r * TSTRIDE))[c4] =
            ((const float4*)g_transT)[r * 64 + src4];
    }

    // Register-resident trans slice: transT[t2][half*128 .. half*128+64)
    float4 tr4[16];
    {
        const float4* src = (const float4*)(g_transT + (size_t)t2 * TAGq) + half * 32;
        #pragma unroll
        for (int k = 0; k < 16; ++k) tr4[k] = src[k];
    }

    const float* febase = feats + (size_t)b * Tq * TAGq;
    float*       hbase  = g_hist + (size_t)b * Tq * TAGq;

    // part0 = feats[b,0,:] + trans[START,:]
    if (tid < TAGq) {
        float p0 = febase[tid] + trans[START_TAG * TAGq + tid];
        partA[tid] = p0;
        hbase[tid] = p0;
    }

    // prefetch emission for t = 1
    float e = __ldcs(febase + (size_t)TAGq + t2);
    __syncthreads();

    const float4* trow_s = (const float4*)(tile + t2 * TSTRIDE) + half * 16;

    float* cur = partA;
    float* nxt = partB;

    for (int t = 1; t < Tq; ++t) {
        // prefetch next step's emission (one full step of latency slack)
        const int tn = (t + 1 < Tq) ? (t + 1) : t;
        float e_nxt = __ldcs(febase + (size_t)tn * TAGq + t2);

        const float2 e2 = make_float2(e, e);
        const float4* p4 = (const float4*)cur + half * 32;  // warp-broadcast

        float a0 = neg_inf(), a1 = a0, a2 = a0, a3 = a0;
        float a4 = a0, a5 = a0, a6 = a0, a7 = a0;

        // j local [0,64): trans from registers
        #pragma unroll
        for (int k = 0; k < 16; ++k) {
            float4 pa = p4[k];
            float4 ta = tr4[k];
            float2 s;
            s = fadd2_(fadd2_(e2, make_float2(ta.x, ta.y)), make_float2(pa.x, pa.y));
            a0 = fmaxf(a0, s.x); a1 = fmaxf(a1, s.y);
            s = fadd2_(fadd2_(e2, make_float2(ta.z, ta.w)), make_float2(pa.z, pa.w));
            a2 = fmaxf(a2, s.x); a3 = fmaxf(a3, s.y);
        }
        // j local [64,128): trans from SMEM tile
        #pragma unroll
        for (int k = 0; k < 16; ++k) {
            float4 pb = p4[16 + k];
            float4 tb = trow_s[k];
            float2 s;
            s = fadd2_(fadd2_(e2, make_float2(tb.x, tb.y)), make_float2(pb.x, pb.y));
            a4 = fmaxf(a4, s.x); a5 = fmaxf(a5, s.y);
            s = fadd2_(fadd2_(e2, make_float2(tb.z, tb.w)), make_float2(pb.z, pb.w));
            a6 = fmaxf(a6, s.x); a7 = fmaxf(a7, s.y);
        }
        float m = fmaxf(fmaxf(fmaxf(a0, a1), fmaxf(a2, a3)),
                        fmaxf(fmaxf(a4, a5), fmaxf(a6, a7)));

        partial[tid] = m;
        __syncthreads();

        if (tid < TAGq) {
            float mm = fmaxf(partial[tid], partial[tid + TAGq]);
            nxt[tid] = mm;
            hbase[(size_t)t * TAGq + tid] = mm;
        }
        __syncthreads();

        float* tp = cur; cur = nxt; nxt = tp;
        e = e_nxt;
    }
}

// ---------------------------------------------------------------------------
// Warp argmax over 256 contiguous values (8 per lane, ascending j), with
// jnp.argmax first-index semantics: lane-local strict-greater ascending scan,
// then redux-max on an order-preserving key; lowest matching lane wins ties.
__device__ __forceinline__ int warp_argmax256(float xv, int xi, float* vmax_out) {
    unsigned kk   = okey(xv);
    unsigned kmax = __reduce_max_sync(0xffffffffu, kk);
    unsigned bal  = __ballot_sync(0xffffffffu, kk == kmax);
    int src = __ffs((int)bal) - 1;
    if (vmax_out)
        *vmax_out = __shfl_sync(0xffffffffu, xv, src);
    return __shfl_sync(0xffffffffu, xi, src);
}

// One warp per batch: final score + full backtrace with bp recomputation.
__global__ void backward_kernel(const float* __restrict__ feats,
                                const int*   __restrict__ mask,
                                float*       __restrict__ out) {
    const int b = blockIdx.x, lane = threadIdx.x;

    // lengths = sum(mask[b,:])  (also warms the mask row into L1)
    int len = 0;
    for (int i = lane; i < Tq; i += 32) len += mask[b * Tq + i];
    #pragma unroll
    for (int o = 16; o; o >>= 1) len += __shfl_down_sync(0xffffffffu, len, o);
    len = __shfl_sync(0xffffffffu, len, 0);
    const int last = len - 1;

    const float* hb = g_hist + (size_t)b * Tq * TAGq;

    // path score / pointer: argmax_j last_part[j] + trans[j][STOP]
    int ptr;
    {
        const float4* lp4 = (const float4*)(hb + (size_t)last * TAGq) + lane * 2;
        const float4* tc4 = (const float4*)(g_transT + STOP_TAG * TAGq) + lane * 2;
        float4 A = lp4[0], B = lp4[1], C = tc4[0], D = tc4[1];
        float v[8] = {A.x + C.x, A.y + C.y, A.z + C.z, A.w + C.w,
                      B.x + D.x, B.y + D.y, B.z + D.z, B.w + D.w};
        float xv = v[0]; int xi = lane * 8;
        #pragma unroll
        for (int k = 1; k < 8; ++k)
            if (v[k] > xv) { xv = v[k]; xi = lane * 8 + k; }
        float bv;
        ptr = warp_argmax256(xv, xi, &bv);
        if (lane == 0) out[b] = bv;
    }

    float* dec = out + Bq;
    if (lane == 0) dec[(size_t)b * Tq + (Tq - 1)] = (float)ptr;

    int cur = ptr;
    for (int i = Tq - 2; i >= 0; --i) {
        // Prefetch-touch rows needed at iteration i-1 (index-predictable,
        // independent of cur): feats[b, i, :] and hist[b, i-1, :].
        // 32 lanes x stride-8 floats = one touch per 32B sector of each 1KB row.
        {
            float d0;
            const float* fr = feats + ((size_t)b * Tq + i) * TAGq + lane * 8;
            asm volatile("ld.global.nc.f32 %0, [%1];" : "=f"(d0) : "l"(fr));
            if (i >= 1) {
                float d1;
                const float* hr = hb + (size_t)(i - 1) * TAGq + lane * 8;
                asm volatile("ld.global.nc.f32 %0, [%1];" : "=f"(d1) : "l"(hr));
            }
        }

        int nv;
        if (i == last) {
            nv = ptr;
        } else if (mask[b * Tq + i + 1] == 0) {
            nv = 0;
        } else {
            // recompute bp at time i+1, column cur — identical arithmetic
            // to the forward pass: (emit + trans) + part
            const float e =
                __ldg(feats + ((size_t)b * Tq + (i + 1)) * TAGq + cur);
            const float4* h4 = (const float4*)(hb + (size_t)i * TAGq) + lane * 2;
            const float4* t4 =
                (const float4*)(g_transT + (size_t)cur * TAGq) + lane * 2;
            float4 H0 = h4[0], H1 = h4[1], T0 = t4[0], T1 = t4[1];
            float v[8] = {(e + T0.x) + H0.x, (e + T0.y) + H0.y,
                          (e + T0.z) + H0.z, (e + T0.w) + H0.w,
                          (e + T1.x) + H1.x, (e + T1.y) + H1.y,
                          (e + T1.z) + H1.z, (e + T1.w) + H1.w};
            float xv = v[0]; int xi = lane * 8;
            #pragma unroll
            for (int k = 1; k < 8; ++k)
                if (v[k] > xv) { xv = v[k]; xi = lane * 8 + k; }
            nv = warp_argmax256(xv, xi, nullptr);
        }
        cur = nv;
        if (lane == 0) dec[(size_t)b * Tq + i] = (float)cur;
    }
}

// ---------------------------------------------------------------------------
extern "C" void kernel_launch(void* const* d_in, const int* in_sizes, int n_in,
                              void* d_out, int out_size) {
    const float* feats = (const float*)d_in[0];   // (128,512,256) f32
    const int*   mask  = (const int*)d_in[1];     // (128,512) i32
    const float* trans = (const float*)d_in[2];   // (256,256) f32
    float* out = (float*)d_out;                   // [128 path_score | 128*512 decode]

    transpose_kernel<<<TAGq, TAGq>>>(trans);

    const size_t smem =
        (size_t)(TAGq * TSTRIDE + 2 * TAGq + NTHREADS) * sizeof(float); // 139264 B
    cudaFuncSetAttribute(forward_kernel,
                         cudaFuncAttributeMaxDynamicSharedMemorySize, (int)smem);
    forward_kernel<<<Bq, NTHREADS, smem>>>(feats, trans);

    backward_kernel<<<Bq, 32>>>(feats, mask, out);
}